// round 16
// baseline (speedup 1.0000x reference)
#include <cuda_runtime.h>
#include <cuda_fp16.h>
#include <math.h>
#include <stdint.h>

#define Bb  8
#define Cc  256
#define P1c 2048
#define P2c 4096
#define CQc 32

// Scratch (device globals: no allocation allowed in kernel_launch)
__device__ __half g_qh[(size_t)Bb * P1c * CQc];   // q hi fp16 [B,P1,32]  1 MB
__device__ __half g_ql[(size_t)Bb * P1c * CQc];   // q lo fp16            1 MB
__device__ __half g_kh[(size_t)Bb * CQc * P2c];   // k hi fp16 [B,32,P2]  2 MB
__device__ __half g_kl[(size_t)Bb * CQc * P2c];   // k lo fp16            2 MB
__device__ __half g_vh[(size_t)Bb * Cc * P1c];    // v fp16 [B,C,P1]      8 MB
__device__ __half g_W [(size_t)Bb * P1c * P2c];   // exp(e)*iz fp16     134 MB
__device__ float  g_part[(size_t)Bb * P1c * 16];  // per-block exp sums   1 MB

__device__ __forceinline__ uint32_t su(const void* p) {
    return (uint32_t)__cvta_generic_to_shared(p);
}

// ---------------------------------------------------------------------------
// K1a: q and k convs merged into one launch. Both emit split fp16 (hi + lo).
// ---------------------------------------------------------------------------
__global__ void __launch_bounds__(256) conv_qk_merged_kernel(
    const float* __restrict__ Wq, const float* __restrict__ bq,
    const float* __restrict__ Wk, const float* __restrict__ bk,
    const float* __restrict__ x1, const float* __restrict__ x2)
{
    __shared__ __align__(16) float sW[Cc * 32];   // [c][o]
    const int b = blockIdx.z;
    const bool is_q = (blockIdx.x < P1c / 256);
    const float* W    = is_q ? Wq : Wk;
    const float* bias = is_q ? bq : bk;
    const int    P    = is_q ? P1c : P2c;
    const int    pblk = is_q ? blockIdx.x : (blockIdx.x - P1c / 256);
    const float* x    = is_q ? x1 : x2;

    for (int i = threadIdx.x; i < Cc * 32; i += 256) {
        int o = i & 31, c = i >> 5;
        sW[i] = W[(size_t)o * Cc + c];
    }
    __syncthreads();

    const int p = pblk * 256 + threadIdx.x;
    const float* xp = x + (size_t)b * Cc * P + p;

    float acc[32];
    #pragma unroll
    for (int o = 0; o < 32; o++) acc[o] = bias[o];

    for (int c = 0; c < Cc; c++) {
        float xv = __ldg(xp + (size_t)c * P);
        const float4* w4 = (const float4*)(sW + c * 32);
        #pragma unroll
        for (int j = 0; j < 8; j++) {
            float4 w = w4[j];
            acc[4*j+0] = fmaf(w.x, xv, acc[4*j+0]);
            acc[4*j+1] = fmaf(w.y, xv, acc[4*j+1]);
            acc[4*j+2] = fmaf(w.z, xv, acc[4*j+2]);
            acc[4*j+3] = fmaf(w.w, xv, acc[4*j+3]);
        }
    }

    if (is_q) {
        const size_t base = ((size_t)b * P1c + p) * 32;
        #pragma unroll
        for (int o = 0; o < 32; o++) {
            __half h = __float2half_rn(acc[o]);
            g_qh[base + o] = h;
            g_ql[base + o] = __float2half_rn(acc[o] - __half2float(h));
        }
    } else {
        const size_t base = (size_t)b * 32 * P2c + p;
        #pragma unroll
        for (int o = 0; o < 32; o++) {
            __half h = __float2half_rn(acc[o]);
            g_kh[base + (size_t)o * P2c] = h;
            g_kl[base + (size_t)o * P2c] = __float2half_rn(acc[o] - __half2float(h));
        }
    }
}

// ---------------------------------------------------------------------------
// K1b: v conv, fp16 out
// ---------------------------------------------------------------------------
__global__ void __launch_bounds__(256) conv1x1_h_kernel(
    const float* __restrict__ W, const float* __restrict__ bias,
    const float* __restrict__ x, __half* __restrict__ out, int P)
{
    __shared__ __align__(16) float sW[Cc * 32];
    const int ochunk = blockIdx.y * 32;
    const int b = blockIdx.z;
    for (int i = threadIdx.x; i < Cc * 32; i += 256) {
        int o = i & 31, c = i >> 5;
        sW[i] = W[(size_t)(ochunk + o) * Cc + c];
    }
    __syncthreads();

    const int p = blockIdx.x * 256 + threadIdx.x;
    const float* xp = x + (size_t)b * Cc * P + p;

    float acc[32];
    #pragma unroll
    for (int o = 0; o < 32; o++) acc[o] = bias[ochunk + o];

    for (int c = 0; c < Cc; c++) {
        float xv = __ldg(xp + (size_t)c * P);
        const float4* w4 = (const float4*)(sW + c * 32);
        #pragma unroll
        for (int j = 0; j < 8; j++) {
            float4 w = w4[j];
            acc[4*j+0] = fmaf(w.x, xv, acc[4*j+0]);
            acc[4*j+1] = fmaf(w.y, xv, acc[4*j+1]);
            acc[4*j+2] = fmaf(w.z, xv, acc[4*j+2]);
            acc[4*j+3] = fmaf(w.w, xv, acc[4*j+3]);
        }
    }

    __half* op = out + ((size_t)b * Cc + ochunk) * P + p;
    #pragma unroll
    for (int o = 0; o < 32; o++) op[(size_t)o * P] = __float2half_rn(acc[o]);
}

// ---------------------------------------------------------------------------
// shared mma helpers
// ---------------------------------------------------------------------------
__device__ __forceinline__ void ldsm_x4(uint32_t* r, uint32_t addr) {
    asm volatile("ldmatrix.sync.aligned.m8n8.x4.shared.b16 {%0,%1,%2,%3}, [%4];"
        : "=r"(r[0]), "=r"(r[1]), "=r"(r[2]), "=r"(r[3]) : "r"(addr));
}
__device__ __forceinline__ void ldsm_x4_t(uint32_t* r, uint32_t addr) {
    asm volatile("ldmatrix.sync.aligned.m8n8.x4.trans.shared.b16 {%0,%1,%2,%3}, [%4];"
        : "=r"(r[0]), "=r"(r[1]), "=r"(r[2]), "=r"(r[3]) : "r"(addr));
}
__device__ __forceinline__ void mma16816(float* c, const uint32_t* a,
                                         uint32_t b0, uint32_t b1) {
    asm volatile(
        "mma.sync.aligned.m16n8k16.row.col.f32.f16.f16.f32 "
        "{%0,%1,%2,%3}, {%4,%5,%6,%7}, {%8,%9}, {%0,%1,%2,%3};"
        : "+f"(c[0]), "+f"(c[1]), "+f"(c[2]), "+f"(c[3])
        : "r"(a[0]), "r"(a[1]), "r"(a[2]), "r"(a[3]), "r"(b0), "r"(b1));
}

// ---------------------------------------------------------------------------
// K2: tensor-core energy GEMM. Tile 64p x 256q2, K=32 single shot.
// e = qhi*khi + qhi*klo + qlo*khi (split fp16 -> fp32-accurate energies).
// WRITE_W = 0: sum pass — per-row exp sums to g_part only, NO e storage.
// WRITE_W = 1: weight pass — inline iz = 1/sum(g_part), recompute e,
//              write W = fp16(exp(e)*iz) directly.
// ---------------------------------------------------------------------------
template<int WRITE_W>
__global__ void __launch_bounds__(256) energy_mma_kernel()
{
    __shared__ __align__(16) uint8_t sqh[4096], sql[4096];    // 64x32 fp16
    __shared__ __align__(16) uint8_t skh[16384], skl[16384];  // 32x256 fp16
    __shared__ float s_sum[64];

    const int b  = blockIdx.z;
    const int p0 = blockIdx.y * 64;
    const int n0 = blockIdx.x * 256;
    const int tid  = threadIdx.x;
    const int wid  = tid >> 5;
    const int lane = tid & 31;
    const int wm  = (wid & 1) * 32;    // warp m offset: 0/32
    const int wnn = (wid >> 1) * 64;   // warp n offset: 0/64/128/192
    const int g  = lane >> 2;
    const int t4 = lane & 3;

    if (!WRITE_W) {
        if (tid < 64) s_sum[tid] = 0.f;
    } else {
        // inline iz: 1 / sum of the 16 per-block partials for this row
        if (tid < 64) {
            const float* pp = g_part + (((size_t)b * P1c + p0 + tid) << 4);
            float s = 0.f;
            #pragma unroll
            for (int j = 0; j < 16; j++) s += pp[j];
            s_sum[tid] = 1.0f / s;
        }
    }

    {
        const int row = tid >> 2, c = tid & 3;
        const size_t src = ((size_t)b * P1c + p0 + row) * CQc + c * 8;
        const int dst = row * 64 + ((c ^ ((row >> 1) & 3)) << 4);
        *(uint4*)&sqh[dst] = *(const uint4*)(g_qh + src);
        *(uint4*)&sql[dst] = *(const uint4*)(g_ql + src);
    }
    #pragma unroll
    for (int j = 0; j < 4; j++) {
        const int idx = j * 256 + tid;
        const int kr = idx >> 5, nc = idx & 31;
        const size_t src = ((size_t)b * CQc + kr) * P2c + n0 + nc * 8;
        const int dst = kr * 512 + ((nc ^ (kr & 7)) << 4);
        *(uint4*)&skh[dst] = *(const uint4*)(g_kh + src);
        *(uint4*)&skl[dst] = *(const uint4*)(g_kl + src);
    }
    __syncthreads();

    float acc[2][8][4];
    #pragma unroll
    for (int mt = 0; mt < 2; mt++)
        #pragma unroll
        for (int nt = 0; nt < 8; nt++)
            #pragma unroll
            for (int j = 0; j < 4; j++) acc[mt][nt][j] = 0.f;

    #pragma unroll
    for (int ks = 0; ks < 2; ks++) {
        uint32_t ah[2][4], al[2][4];
        const int mr = wm + (lane & 15);
        const int kc = ks * 2 + ((lane >> 4) & 1);
        #pragma unroll
        for (int mt = 0; mt < 2; mt++) {
            const int r = mr + mt * 16;
            const int off = r * 64 + ((kc ^ ((r >> 1) & 3)) << 4);
            ldsm_x4(ah[mt], su(sqh + off));
            ldsm_x4(al[mt], su(sql + off));
        }
        const int kk = ks * 16 + (lane & 7) + ((lane >> 3) & 1) * 8;
        #pragma unroll
        for (int np = 0; np < 4; np++) {
            const int nch = (wnn + np * 16 + ((lane >> 4) & 1) * 8) >> 3;
            const int boff = kk * 512 + ((nch ^ (kk & 7)) << 4);
            uint32_t bh[4], bl[4];
            ldsm_x4_t(bh, su(skh + boff));
            ldsm_x4_t(bl, su(skl + boff));
            #pragma unroll
            for (int mt = 0; mt < 2; mt++) {
                #pragma unroll
                for (int h = 0; h < 2; h++) {
                    float* a4 = acc[mt][np * 2 + h];
                    mma16816(a4, ah[mt], bh[h*2], bh[h*2+1]);   // qhi*khi
                    mma16816(a4, ah[mt], bl[h*2], bl[h*2+1]);   // qhi*klo
                    mma16816(a4, al[mt], bh[h*2], bh[h*2+1]);   // qlo*khi
                }
            }
        }
    }

    if (!WRITE_W) {
        float srow[4] = {0.f, 0.f, 0.f, 0.f};
        #pragma unroll
        for (int mt = 0; mt < 2; mt++)
            #pragma unroll
            for (int np = 0; np < 4; np++)
                #pragma unroll
                for (int h = 0; h < 2; h++) {
                    const float* a4 = acc[mt][np * 2 + h];
                    srow[mt*2+0] += __expf(a4[0]) + __expf(a4[1]);
                    srow[mt*2+1] += __expf(a4[2]) + __expf(a4[3]);
                }
        #pragma unroll
        for (int i = 0; i < 4; i++) {
            srow[i] += __shfl_xor_sync(0xffffffffu, srow[i], 1);
            srow[i] += __shfl_xor_sync(0xffffffffu, srow[i], 2);
        }
        if (t4 == 0) {
            #pragma unroll
            for (int i = 0; i < 4; i++) {
                const int r = wm + (i >> 1) * 16 + g + (i & 1) * 8;
                atomicAdd(&s_sum[r], srow[i]);
            }
        }
        __syncthreads();
        if (tid < 64)
            g_part[(((size_t)b * P1c + p0 + tid) << 4) + blockIdx.x] = s_sum[tid];
    } else {
        float izv[2][2];
        #pragma unroll
        for (int mt = 0; mt < 2; mt++) {
            izv[mt][0] = s_sum[wm + mt * 16 + g];
            izv[mt][1] = s_sum[wm + mt * 16 + g + 8];
        }
        #pragma unroll
        for (int mt = 0; mt < 2; mt++)
            #pragma unroll
            for (int np = 0; np < 4; np++)
                #pragma unroll
                for (int h = 0; h < 2; h++) {
                    const float* a4 = acc[mt][np * 2 + h];
                    const int r0 = wm + mt * 16 + g;
                    const int c0 = n0 + wnn + np * 16 + h * 8 + 2 * t4;
                    const size_t o0 = ((size_t)b * P1c + p0 + r0) * P2c + c0;
                    const size_t o1 = o0 + (size_t)8 * P2c;
                    __half2 w0 = __floats2half2_rn(__expf(a4[0]) * izv[mt][0],
                                                   __expf(a4[1]) * izv[mt][0]);
                    __half2 w1 = __floats2half2_rn(__expf(a4[2]) * izv[mt][1],
                                                   __expf(a4[3]) * izv[mt][1]);
                    *(__half2*)(g_W + o0) = w0;
                    *(__half2*)(g_W + o1) = w1;
                }
    }
}

// ---------------------------------------------------------------------------
// K3: fp16 mma.sync m16n8k16 GEMM, 3-stage cp.async pipeline, BK=64.
// 512 threads/CTA: 16 warps in 4m x 4n layout, warp tile 32x32. acc shrinks
// to 32 regs/thread so __launch_bounds__(512,2) holds 2 CTAs/SM at the
// 64-reg cap -> 32 warps/SM (2x the latency hiding of the 256-thread
// version). Same verified swizzles/fragment math; stage = 16KB A + 16KB B.
// ---------------------------------------------------------------------------
#define BK3 64
#define NCH (P1c / BK3)
#define NST 3
#define A_ST 16384
#define STAGE_BYTES 32768

__device__ __forceinline__ void cp16(uint32_t dst, const void* src) {
    asm volatile("cp.async.cg.shared.global [%0], [%1], 16;"
                 :: "r"(dst), "l"(src) : "memory");
}
__device__ __forceinline__ void cp_commit() {
    asm volatile("cp.async.commit_group;" ::: "memory");
}
__device__ __forceinline__ void cp_wait1() {
    asm volatile("cp.async.wait_group 1;" ::: "memory");
}

__global__ void __launch_bounds__(512, 2) out_gemm_h(
    const float* __restrict__ x2, const float* __restrict__ alpha,
    float* __restrict__ out)
{
    extern __shared__ __align__(16) uint8_t smem[];   // NST * 32KB

    const int b  = blockIdx.z;
    const int m0 = blockIdx.y * 128;
    const int n0 = blockIdx.x * 128;
    const int tid  = threadIdx.x;
    const int wid  = tid >> 5;
    const int lane = tid & 31;
    const int wm = (wid >> 2) * 32;   // 0,32,64,96
    const int wn = (wid & 3) * 32;    // 0,32,64,96

    const __half* Abase = g_vh + ((size_t)b * Cc  + m0) * (size_t)P1c;
    const __half* Wb    = g_W  + (size_t)b * P1c * P2c + n0;

    float acc[2][4][4];
    #pragma unroll
    for (int mt = 0; mt < 2; mt++)
        #pragma unroll
        for (int nt = 0; nt < 4; nt++)
            #pragma unroll
            for (int j = 0; j < 4; j++) acc[mt][nt][j] = 0.f;

    // stage issue: 4 cp16/thread (2 A + 2 B) into per-subtile swizzled layout
    auto issue = [&](int ch) {
        uint8_t* st = smem + (ch % NST) * STAGE_BYTES;
        const int k0 = ch * BK3;
        #pragma unroll
        for (int j = 0; j < 2; j++) {              // A: 1024 chunks total
            const int idx = j * 512 + tid;
            const int row = idx >> 3, c16 = idx & 7;
            const int sub = c16 >> 1, aC = c16 & 1;
            cp16(su(st + sub * 4096 + row * 32 + ((aC ^ ((row >> 2) & 1)) << 4)),
                 Abase + (size_t)row * P1c + k0 + c16 * 8);
        }
        #pragma unroll
        for (int j = 0; j < 2; j++) {              // B: 1024 chunks total
            const int idx = j * 512 + tid;
            const int kkt = idx >> 4, nch = idx & 15;
            const int sub = kkt >> 4, kk = kkt & 15;
            cp16(su(st + A_ST + sub * 4096 + kk * 256 + ((nch ^ (kk & 7)) << 4)),
                 Wb + (size_t)(k0 + kkt) * P2c + nch * 8);
        }
    };

    #pragma unroll
    for (int c = 0; c < NST - 1; c++) {
        issue(c);
        cp_commit();
    }

    for (int ch = 0; ch < NCH; ch++) {
        cp_wait1();
        __syncthreads();

        const uint8_t* base = smem + (ch % NST) * STAGE_BYTES;
        #pragma unroll
        for (int s = 0; s < 4; s++) {
            uint32_t a[2][4];
            #pragma unroll
            for (int mt = 0; mt < 2; mt++) {
                const int mr = wm + mt * 16 + (lane & 7) + ((lane >> 3) & 1) * 8;
                const int clog = (lane >> 4) & 1;
                ldsm_x4(a[mt], su(base + s * 4096 + mr * 32 +
                                  ((clog ^ ((mr >> 2) & 1)) << 4)));
            }
            const int kk = (lane & 7) + ((lane >> 3) & 1) * 8;
            #pragma unroll
            for (int np = 0; np < 2; np++) {
                const int nch = (wn + np * 16 + ((lane >> 4) & 1) * 8) >> 3;
                uint32_t br[4];
                ldsm_x4_t(br, su(base + A_ST + s * 4096 + kk * 256 +
                                 ((nch ^ (kk & 7)) << 4)));
                mma16816(acc[0][np * 2],     a[0], br[0], br[1]);
                mma16816(acc[1][np * 2],     a[1], br[0], br[1]);
                mma16816(acc[0][np * 2 + 1], a[0], br[2], br[3]);
                mma16816(acc[1][np * 2 + 1], a[1], br[2], br[3]);
            }
        }

        if (ch + NST - 1 < NCH) issue(ch + NST - 1);
        cp_commit();
    }

    const float al = __ldg(alpha);
    const int g  = lane >> 2;
    const int t4 = lane & 3;
    #pragma unroll
    for (int mt = 0; mt < 2; mt++) {
        #pragma unroll
        for (int nt = 0; nt < 4; nt++) {
            const int r0 = m0 + wm + mt * 16 + g;
            const int c0 = n0 + wn + nt * 8 + 2 * t4;
            const size_t o0 = ((size_t)b * Cc + r0) * P2c + c0;
            const size_t o1 = o0 + (size_t)8 * P2c;
            float2 x0 = *(const float2*)(x2 + o0);
            float2 x1 = *(const float2*)(x2 + o1);
            float2 w0, w1;
            w0.x = fmaf(al, acc[mt][nt][0], x0.x);
            w0.y = fmaf(al, acc[mt][nt][1], x0.y);
            w1.x = fmaf(al, acc[mt][nt][2], x1.x);
            w1.y = fmaf(al, acc[mt][nt][3], x1.y);
            *(float2*)(out + o0) = w0;
            *(float2*)(out + o1) = w1;
        }
    }
}

// ---------------------------------------------------------------------------
extern "C" void kernel_launch(void* const* d_in, const int* in_sizes, int n_in,
                              void* d_out, int out_size)
{
    (void)in_sizes; (void)n_in; (void)out_size;
    const float* x1    = (const float*)d_in[0];
    const float* x2    = (const float*)d_in[1];
    const float* Wq    = (const float*)d_in[2];
    const float* bq    = (const float*)d_in[3];
    const float* Wk    = (const float*)d_in[4];
    const float* bk    = (const float*)d_in[5];
    const float* Wv    = (const float*)d_in[6];
    const float* bv    = (const float*)d_in[7];
    const float* alpha = (const float*)d_in[8];
    float* out = (float*)d_out;

    void* pv = nullptr;
    cudaGetSymbolAddress(&pv, g_vh);

    cudaFuncSetAttribute(out_gemm_h,
                         cudaFuncAttributeMaxDynamicSharedMemorySize,
                         NST * STAGE_BYTES);

    conv_qk_merged_kernel<<<dim3(P1c / 256 + P2c / 256, 1, Bb), 256>>>(
        Wq, bq, Wk, bk, x1, x2);
    conv1x1_h_kernel<<<dim3(P1c / 256, Cc / 32, Bb), 256>>>(
        Wv, bv, x1, (__half*)pv, P1c);

    energy_mma_kernel<0><<<dim3(P2c / 256, P1c / 64, Bb), 256>>>();   // sums
    energy_mma_kernel<1><<<dim3(P2c / 256, P1c / 64, Bb), 256>>>();   // weights (iz inline)

    out_gemm_h<<<dim3(P2c / 128, Cc / 128, Bb), 512, NST * STAGE_BYTES>>>(x2, alpha, out);
}

// round 17
// speedup vs baseline: 1.1495x; 1.1495x over previous
#include <cuda_runtime.h>
#include <cuda_fp16.h>
#include <math.h>
#include <stdint.h>

#define Bb  8
#define Cc  256
#define P1c 2048
#define P2c 4096
#define CQc 32

// Scratch (device globals: no allocation allowed in kernel_launch)
__device__ __half g_qh[(size_t)Bb * P1c * CQc];   // q hi fp16 [B,P1,32]  1 MB
__device__ __half g_ql[(size_t)Bb * P1c * CQc];   // q lo fp16            1 MB
__device__ __half g_kh[(size_t)Bb * CQc * P2c];   // k hi fp16 [B,32,P2]  2 MB
__device__ __half g_kl[(size_t)Bb * CQc * P2c];   // k lo fp16            2 MB
__device__ __half g_vh[(size_t)Bb * Cc * P1c];    // v fp16 [B,C,P1]      8 MB
__device__ __half g_W [(size_t)Bb * P1c * P2c];   // exp(e)*iz fp16     134 MB
__device__ float  g_part[(size_t)Bb * P1c * 16];  // per-block exp sums   1 MB

__device__ __forceinline__ uint32_t su(const void* p) {
    return (uint32_t)__cvta_generic_to_shared(p);
}

// ---------------------------------------------------------------------------
// K1: ALL THREE convs in one launch (fills the chip once).
// blockIdx.x decode: [0,8) q | [8,24) k | [24,88) v (8 ochunks x 8 pblks).
// q/k emit split fp16 (hi+lo); v emits plain fp16.
// ---------------------------------------------------------------------------
__global__ void __launch_bounds__(256) conv_all_kernel(
    const float* __restrict__ Wq, const float* __restrict__ bq,
    const float* __restrict__ Wk, const float* __restrict__ bk,
    const float* __restrict__ Wv, const float* __restrict__ bv,
    const float* __restrict__ x1, const float* __restrict__ x2)
{
    __shared__ __align__(16) float sW[Cc * 32];   // [c][o]
    const int b  = blockIdx.z;
    const int bx = blockIdx.x;

    int mode, pblk, ochunk;
    const float *W, *bias, *x;
    int P;
    if (bx < 8)       { mode = 0; pblk = bx;            ochunk = 0;
                        W = Wq; bias = bq; x = x1; P = P1c; }
    else if (bx < 24) { mode = 1; pblk = bx - 8;        ochunk = 0;
                        W = Wk; bias = bk; x = x2; P = P2c; }
    else              { mode = 2; pblk = (bx - 24) & 7; ochunk = ((bx - 24) >> 3) * 32;
                        W = Wv; bias = bv; x = x1; P = P1c; }

    for (int i = threadIdx.x; i < Cc * 32; i += 256) {
        int o = i & 31, c = i >> 5;
        sW[i] = W[(size_t)(ochunk + o) * Cc + c];
    }
    __syncthreads();

    const int p = pblk * 256 + threadIdx.x;
    const float* xp = x + (size_t)b * Cc * P + p;

    float acc[32];
    #pragma unroll
    for (int o = 0; o < 32; o++) acc[o] = bias[ochunk + o];

    for (int c = 0; c < Cc; c++) {
        float xv = __ldg(xp + (size_t)c * P);
        const float4* w4 = (const float4*)(sW + c * 32);
        #pragma unroll
        for (int j = 0; j < 8; j++) {
            float4 w = w4[j];
            acc[4*j+0] = fmaf(w.x, xv, acc[4*j+0]);
            acc[4*j+1] = fmaf(w.y, xv, acc[4*j+1]);
            acc[4*j+2] = fmaf(w.z, xv, acc[4*j+2]);
            acc[4*j+3] = fmaf(w.w, xv, acc[4*j+3]);
        }
    }

    if (mode == 0) {
        const size_t base = ((size_t)b * P1c + p) * 32;
        #pragma unroll
        for (int o = 0; o < 32; o++) {
            __half h = __float2half_rn(acc[o]);
            g_qh[base + o] = h;
            g_ql[base + o] = __float2half_rn(acc[o] - __half2float(h));
        }
    } else if (mode == 1) {
        const size_t base = (size_t)b * 32 * P2c + p;
        #pragma unroll
        for (int o = 0; o < 32; o++) {
            __half h = __float2half_rn(acc[o]);
            g_kh[base + (size_t)o * P2c] = h;
            g_kl[base + (size_t)o * P2c] = __float2half_rn(acc[o] - __half2float(h));
        }
    } else {
        __half* op = g_vh + ((size_t)b * Cc + ochunk) * P1c + p;
        #pragma unroll
        for (int o = 0; o < 32; o++) op[(size_t)o * P1c] = __float2half_rn(acc[o]);
    }
}

// ---------------------------------------------------------------------------
// shared mma helpers
// ---------------------------------------------------------------------------
__device__ __forceinline__ void ldsm_x4(uint32_t* r, uint32_t addr) {
    asm volatile("ldmatrix.sync.aligned.m8n8.x4.shared.b16 {%0,%1,%2,%3}, [%4];"
        : "=r"(r[0]), "=r"(r[1]), "=r"(r[2]), "=r"(r[3]) : "r"(addr));
}
__device__ __forceinline__ void ldsm_x4_t(uint32_t* r, uint32_t addr) {
    asm volatile("ldmatrix.sync.aligned.m8n8.x4.trans.shared.b16 {%0,%1,%2,%3}, [%4];"
        : "=r"(r[0]), "=r"(r[1]), "=r"(r[2]), "=r"(r[3]) : "r"(addr));
}
__device__ __forceinline__ void mma16816(float* c, const uint32_t* a,
                                         uint32_t b0, uint32_t b1) {
    asm volatile(
        "mma.sync.aligned.m16n8k16.row.col.f32.f16.f16.f32 "
        "{%0,%1,%2,%3}, {%4,%5,%6,%7}, {%8,%9}, {%0,%1,%2,%3};"
        : "+f"(c[0]), "+f"(c[1]), "+f"(c[2]), "+f"(c[3])
        : "r"(a[0]), "r"(a[1]), "r"(a[2]), "r"(a[3]), "r"(b0), "r"(b1));
}

// ---------------------------------------------------------------------------
// K2: tensor-core energy GEMM. Tile 64p x 256q2, K=32 single shot.
// e = qhi*khi + qhi*klo + qlo*khi (split fp16 -> fp32-accurate energies).
// WRITE_W = 0: sum pass — per-row exp sums to g_part only, NO e storage.
// WRITE_W = 1: weight pass — inline iz = 1/sum(g_part), recompute e,
//              write W = fp16(exp(e)*iz) directly.
// ---------------------------------------------------------------------------
template<int WRITE_W>
__global__ void __launch_bounds__(256) energy_mma_kernel()
{
    __shared__ __align__(16) uint8_t sqh[4096], sql[4096];    // 64x32 fp16
    __shared__ __align__(16) uint8_t skh[16384], skl[16384];  // 32x256 fp16
    __shared__ float s_sum[64];

    const int b  = blockIdx.z;
    const int p0 = blockIdx.y * 64;
    const int n0 = blockIdx.x * 256;
    const int tid  = threadIdx.x;
    const int wid  = tid >> 5;
    const int lane = tid & 31;
    const int wm  = (wid & 1) * 32;    // warp m offset: 0/32
    const int wnn = (wid >> 1) * 64;   // warp n offset: 0/64/128/192
    const int g  = lane >> 2;
    const int t4 = lane & 3;

    if (!WRITE_W) {
        if (tid < 64) s_sum[tid] = 0.f;
    } else {
        if (tid < 64) {
            const float* pp = g_part + (((size_t)b * P1c + p0 + tid) << 4);
            float s = 0.f;
            #pragma unroll
            for (int j = 0; j < 16; j++) s += pp[j];
            s_sum[tid] = 1.0f / s;
        }
    }

    {
        const int row = tid >> 2, c = tid & 3;
        const size_t src = ((size_t)b * P1c + p0 + row) * CQc + c * 8;
        const int dst = row * 64 + ((c ^ ((row >> 1) & 3)) << 4);
        *(uint4*)&sqh[dst] = *(const uint4*)(g_qh + src);
        *(uint4*)&sql[dst] = *(const uint4*)(g_ql + src);
    }
    #pragma unroll
    for (int j = 0; j < 4; j++) {
        const int idx = j * 256 + tid;
        const int kr = idx >> 5, nc = idx & 31;
        const size_t src = ((size_t)b * CQc + kr) * P2c + n0 + nc * 8;
        const int dst = kr * 512 + ((nc ^ (kr & 7)) << 4);
        *(uint4*)&skh[dst] = *(const uint4*)(g_kh + src);
        *(uint4*)&skl[dst] = *(const uint4*)(g_kl + src);
    }
    __syncthreads();

    float acc[2][8][4];
    #pragma unroll
    for (int mt = 0; mt < 2; mt++)
        #pragma unroll
        for (int nt = 0; nt < 8; nt++)
            #pragma unroll
            for (int j = 0; j < 4; j++) acc[mt][nt][j] = 0.f;

    #pragma unroll
    for (int ks = 0; ks < 2; ks++) {
        uint32_t ah[2][4], al[2][4];
        const int mr = wm + (lane & 15);
        const int kc = ks * 2 + ((lane >> 4) & 1);
        #pragma unroll
        for (int mt = 0; mt < 2; mt++) {
            const int r = mr + mt * 16;
            const int off = r * 64 + ((kc ^ ((r >> 1) & 3)) << 4);
            ldsm_x4(ah[mt], su(sqh + off));
            ldsm_x4(al[mt], su(sql + off));
        }
        const int kk = ks * 16 + (lane & 7) + ((lane >> 3) & 1) * 8;
        #pragma unroll
        for (int np = 0; np < 4; np++) {
            const int nch = (wnn + np * 16 + ((lane >> 4) & 1) * 8) >> 3;
            const int boff = kk * 512 + ((nch ^ (kk & 7)) << 4);
            uint32_t bh[4], bl[4];
            ldsm_x4_t(bh, su(skh + boff));
            ldsm_x4_t(bl, su(skl + boff));
            #pragma unroll
            for (int mt = 0; mt < 2; mt++) {
                #pragma unroll
                for (int h = 0; h < 2; h++) {
                    float* a4 = acc[mt][np * 2 + h];
                    mma16816(a4, ah[mt], bh[h*2], bh[h*2+1]);   // qhi*khi
                    mma16816(a4, ah[mt], bl[h*2], bl[h*2+1]);   // qhi*klo
                    mma16816(a4, al[mt], bh[h*2], bh[h*2+1]);   // qlo*khi
                }
            }
        }
    }

    if (!WRITE_W) {
        float srow[4] = {0.f, 0.f, 0.f, 0.f};
        #pragma unroll
        for (int mt = 0; mt < 2; mt++)
            #pragma unroll
            for (int np = 0; np < 4; np++)
                #pragma unroll
                for (int h = 0; h < 2; h++) {
                    const float* a4 = acc[mt][np * 2 + h];
                    srow[mt*2+0] += __expf(a4[0]) + __expf(a4[1]);
                    srow[mt*2+1] += __expf(a4[2]) + __expf(a4[3]);
                }
        #pragma unroll
        for (int i = 0; i < 4; i++) {
            srow[i] += __shfl_xor_sync(0xffffffffu, srow[i], 1);
            srow[i] += __shfl_xor_sync(0xffffffffu, srow[i], 2);
        }
        if (t4 == 0) {
            #pragma unroll
            for (int i = 0; i < 4; i++) {
                const int r = wm + (i >> 1) * 16 + g + (i & 1) * 8;
                atomicAdd(&s_sum[r], srow[i]);
            }
        }
        __syncthreads();
        if (tid < 64)
            g_part[(((size_t)b * P1c + p0 + tid) << 4) + blockIdx.x] = s_sum[tid];
    } else {
        float izv[2][2];
        #pragma unroll
        for (int mt = 0; mt < 2; mt++) {
            izv[mt][0] = s_sum[wm + mt * 16 + g];
            izv[mt][1] = s_sum[wm + mt * 16 + g + 8];
        }
        #pragma unroll
        for (int mt = 0; mt < 2; mt++)
            #pragma unroll
            for (int np = 0; np < 4; np++)
                #pragma unroll
                for (int h = 0; h < 2; h++) {
                    const float* a4 = acc[mt][np * 2 + h];
                    const int r0 = wm + mt * 16 + g;
                    const int c0 = n0 + wnn + np * 16 + h * 8 + 2 * t4;
                    const size_t o0 = ((size_t)b * P1c + p0 + r0) * P2c + c0;
                    const size_t o1 = o0 + (size_t)8 * P2c;
                    __half2 w0 = __floats2half2_rn(__expf(a4[0]) * izv[mt][0],
                                                   __expf(a4[1]) * izv[mt][0]);
                    __half2 w1 = __floats2half2_rn(__expf(a4[2]) * izv[mt][1],
                                                   __expf(a4[3]) * izv[mt][1]);
                    *(__half2*)(g_W + o0) = w0;
                    *(__half2*)(g_W + o1) = w1;
                }
    }
}

// ---------------------------------------------------------------------------
// K3: fp16 mma.sync m16n8k16 GEMM, 3-stage cp.async pipeline, BK=64,
// 256 threads (R15 best base) + FRAGMENT DOUBLE BUFFERING: subtile s+1's
// ldsm issue before subtile s's mma block, breaking the serial ldsm->mma
// scoreboard chain that was exposing ~30cyc per subtile step.
// ---------------------------------------------------------------------------
#define BK3 64
#define NCH (P1c / BK3)
#define NST 3
#define A_ST 16384
#define STAGE_BYTES 32768

__device__ __forceinline__ void cp16(uint32_t dst, const void* src) {
    asm volatile("cp.async.cg.shared.global [%0], [%1], 16;"
                 :: "r"(dst), "l"(src) : "memory");
}
__device__ __forceinline__ void cp_commit() {
    asm volatile("cp.async.commit_group;" ::: "memory");
}
__device__ __forceinline__ void cp_wait1() {
    asm volatile("cp.async.wait_group 1;" ::: "memory");
}

__global__ void __launch_bounds__(256, 2) out_gemm_h(
    const float* __restrict__ x2, const float* __restrict__ alpha,
    float* __restrict__ out)
{
    extern __shared__ __align__(16) uint8_t smem[];   // NST * 32KB

    const int b  = blockIdx.z;
    const int m0 = blockIdx.y * 128;
    const int n0 = blockIdx.x * 128;
    const int tid  = threadIdx.x;
    const int wid  = tid >> 5;
    const int lane = tid & 31;
    const int wm = (wid >> 1) * 32;
    const int wn = (wid & 1) * 64;

    const __half* Abase = g_vh + ((size_t)b * Cc  + m0) * (size_t)P1c;
    const __half* Wb    = g_W  + (size_t)b * P1c * P2c + n0;

    // loop-invariant swizzled fragment offsets (within a 4KB subtile)
    int aoff[2];
    #pragma unroll
    for (int mt = 0; mt < 2; mt++) {
        const int mr = wm + mt * 16 + (lane & 7) + ((lane >> 3) & 1) * 8;
        const int clog = (lane >> 4) & 1;
        aoff[mt] = mr * 32 + ((clog ^ ((mr >> 2) & 1)) << 4);
    }
    const int kk = (lane & 7) + ((lane >> 3) & 1) * 8;
    int boff[4];
    #pragma unroll
    for (int np = 0; np < 4; np++) {
        const int nch = (wn + np * 16 + ((lane >> 4) & 1) * 8) >> 3;
        boff[np] = A_ST + kk * 256 + ((nch ^ (kk & 7)) << 4);
    }

    float acc[2][8][4];
    #pragma unroll
    for (int mt = 0; mt < 2; mt++)
        #pragma unroll
        for (int nt = 0; nt < 8; nt++)
            #pragma unroll
            for (int j = 0; j < 4; j++) acc[mt][nt][j] = 0.f;

    auto issue = [&](int ch) {
        uint8_t* st = smem + (ch % NST) * STAGE_BYTES;
        const int k0 = ch * BK3;
        #pragma unroll
        for (int j = 0; j < 4; j++) {              // A: 1024 chunks total
            const int idx = j * 256 + tid;
            const int row = idx >> 3, c16 = idx & 7;
            const int sub = c16 >> 1, aC = c16 & 1;
            cp16(su(st + sub * 4096 + row * 32 + ((aC ^ ((row >> 2) & 1)) << 4)),
                 Abase + (size_t)row * P1c + k0 + c16 * 8);
        }
        #pragma unroll
        for (int j = 0; j < 4; j++) {              // B: 1024 chunks total
            const int idx = j * 256 + tid;
            const int kkt = idx >> 4, nch = idx & 15;
            const int sub = kkt >> 4, kx = kkt & 15;
            cp16(su(st + A_ST + sub * 4096 + kx * 256 + ((nch ^ (kx & 7)) << 4)),
                 Wb + (size_t)(k0 + kkt) * P2c + nch * 8);
        }
    };

    #pragma unroll
    for (int c = 0; c < NST - 1; c++) {
        issue(c);
        cp_commit();
    }

    for (int ch = 0; ch < NCH; ch++) {
        cp_wait1();
        __syncthreads();

        const uint8_t* base = smem + (ch % NST) * STAGE_BYTES;

        uint32_t fa[2][2][4];   // [buf][mt][4]
        uint32_t fb[2][4][4];   // [buf][np][4]

        // preload subtile 0 fragments
        #pragma unroll
        for (int mt = 0; mt < 2; mt++) ldsm_x4(fa[0][mt], su(base + aoff[mt]));
        #pragma unroll
        for (int np = 0; np < 4; np++) ldsm_x4_t(fb[0][np], su(base + boff[np]));

        #pragma unroll
        for (int s = 0; s < 4; s++) {
            const int cur = s & 1, nxt = cur ^ 1;
            if (s < 3) {   // issue next subtile's loads BEFORE consuming cur
                const uint8_t* nb = base + (s + 1) * 4096;
                #pragma unroll
                for (int mt = 0; mt < 2; mt++)
                    ldsm_x4(fa[nxt][mt], su(nb + aoff[mt]));
                #pragma unroll
                for (int np = 0; np < 4; np++)
                    ldsm_x4_t(fb[nxt][np], su(nb + boff[np]));
            }
            #pragma unroll
            for (int np = 0; np < 4; np++) {
                mma16816(acc[0][np * 2],     fa[cur][0], fb[cur][np][0], fb[cur][np][1]);
                mma16816(acc[1][np * 2],     fa[cur][1], fb[cur][np][0], fb[cur][np][1]);
                mma16816(acc[0][np * 2 + 1], fa[cur][0], fb[cur][np][2], fb[cur][np][3]);
                mma16816(acc[1][np * 2 + 1], fa[cur][1], fb[cur][np][2], fb[cur][np][3]);
            }
        }

        if (ch + NST - 1 < NCH) issue(ch + NST - 1);
        cp_commit();
    }

    const float al = __ldg(alpha);
    const int g  = lane >> 2;
    const int t4 = lane & 3;
    #pragma unroll
    for (int mt = 0; mt < 2; mt++) {
        #pragma unroll
        for (int nt = 0; nt < 8; nt++) {
            const int r0 = m0 + wm + mt * 16 + g;
            const int c0 = n0 + wn + nt * 8 + 2 * t4;
            const size_t o0 = ((size_t)b * Cc + r0) * P2c + c0;
            const size_t o1 = o0 + (size_t)8 * P2c;
            float2 x0 = *(const float2*)(x2 + o0);
            float2 x1 = *(const float2*)(x2 + o1);
            float2 w0, w1;
            w0.x = fmaf(al, acc[mt][nt][0], x0.x);
            w0.y = fmaf(al, acc[mt][nt][1], x0.y);
            w1.x = fmaf(al, acc[mt][nt][2], x1.x);
            w1.y = fmaf(al, acc[mt][nt][3], x1.y);
            *(float2*)(out + o0) = w0;
            *(float2*)(out + o1) = w1;
        }
    }
}

// ---------------------------------------------------------------------------
extern "C" void kernel_launch(void* const* d_in, const int* in_sizes, int n_in,
                              void* d_out, int out_size)
{
    (void)in_sizes; (void)n_in; (void)out_size;
    const float* x1    = (const float*)d_in[0];
    const float* x2    = (const float*)d_in[1];
    const float* Wq    = (const float*)d_in[2];
    const float* bq    = (const float*)d_in[3];
    const float* Wk    = (const float*)d_in[4];
    const float* bk    = (const float*)d_in[5];
    const float* Wv    = (const float*)d_in[6];
    const float* bv    = (const float*)d_in[7];
    const float* alpha = (const float*)d_in[8];
    float* out = (float*)d_out;

    cudaFuncSetAttribute(out_gemm_h,
                         cudaFuncAttributeMaxDynamicSharedMemorySize,
                         NST * STAGE_BYTES);

    conv_all_kernel<<<dim3(88, 1, Bb), 256>>>(Wq, bq, Wk, bk, Wv, bv, x1, x2);

    energy_mma_kernel<0><<<dim3(P2c / 256, P1c / 64, Bb), 256>>>();   // sums
    energy_mma_kernel<1><<<dim3(P2c / 256, P1c / 64, Bb), 256>>>();   // weights (iz inline)

    out_gemm_h<<<dim3(P2c / 128, Cc / 128, Bb), 256, NST * STAGE_BYTES>>>(x2, alpha, out);
}